// round 1
// baseline (speedup 1.0000x reference)
#include <cuda_runtime.h>
#include <cstddef>

// Problem: B=4, H=8, N=256, D=32
//   scores[b,h,i,j,d] = q[b,h,i,d]*k[b,h,j,d]*edges[b,h,i,j,d]
//   logits = sum_d(scores)/sqrt(D) + mask[b,i,j]; attn = softmax_j
//   out[b,i,h*D+d]      = sum_j attn[b,h,i,j]*v[b,h,j,d]
//   edge_out[b,j,i,h*D+d] = scores[b,h,i,j,d]
// d_out = [ out (B*N*H*D) | edge_out (B*N*N*H*D) ]

#define FULLM 0xffffffffu

__global__ __launch_bounds__(256)
void edge_attn_kernel(const float* __restrict__ q,
                      const float* __restrict__ k,
                      const float* __restrict__ v,
                      const float* __restrict__ e,
                      const float* __restrict__ mask,
                      float* __restrict__ out,
                      float* __restrict__ eout)
{
    const int lane = threadIdx.x & 31;
    const int warp = blockIdx.x * (blockDim.x >> 5) + (threadIdx.x >> 5); // 0..8191
    const int i  = warp & 255;     // query row
    const int bh = warp >> 8;      // 0..31
    const int h  = bh & 7;
    const int b  = bh >> 3;

    const float qd = q[((size_t)bh * 256 + i) * 32 + lane];
    const float* __restrict__ kb = k + (size_t)bh * 256 * 32;
    const float* __restrict__ vb = v + (size_t)bh * 256 * 32;
    const float* __restrict__ eb = e + ((size_t)bh * 256 + i) * 256 * 32;
    const float* __restrict__ mr = mask + ((size_t)b * 256 + i) * 256;
    // edge_out[b, j, i, h*32+lane]: offset = (b*65536 + j*256 + i)*256 + h*32 + lane
    float* __restrict__ eo = eout + ((size_t)b * 65536 + i) * 256 + (size_t)h * 32 + lane;

    float lg[8];

    #pragma unroll
    for (int jo = 0; jo < 8; ++jo) {
        #pragma unroll 4
        for (int ji = 0; ji < 32; ++ji) {
            const int j = jo * 32 + ji;
            float s = qd * kb[j * 32 + lane] * eb[j * 32 + lane];
            eo[(size_t)j * 65536] = s;           // full 128B line per warp
            float t = s;
            t += __shfl_xor_sync(FULLM, t, 16);
            t += __shfl_xor_sync(FULLM, t, 8);
            t += __shfl_xor_sync(FULLM, t, 4);
            t += __shfl_xor_sync(FULLM, t, 2);
            t += __shfl_xor_sync(FULLM, t, 1);
            // all lanes hold the full sum; lane ji keeps logit j
            float logit = t * 0.17677669529663687f + mr[j];  // 1/sqrt(32)
            if (lane == ji) lg[jo] = logit;
        }
    }

    // softmax over the 256 logits (8 per lane)
    float m = lg[0];
    #pragma unroll
    for (int r = 1; r < 8; ++r) m = fmaxf(m, lg[r]);
    #pragma unroll
    for (int o = 16; o; o >>= 1) m = fmaxf(m, __shfl_xor_sync(FULLM, m, o));

    float ssum = 0.f;
    #pragma unroll
    for (int r = 0; r < 8; ++r) { lg[r] = __expf(lg[r] - m); ssum += lg[r]; }
    #pragma unroll
    for (int o = 16; o; o >>= 1) ssum += __shfl_xor_sync(FULLM, ssum, o);
    const float inv = 1.0f / ssum;

    // out = attn @ v  (broadcast p_j from owning lane, lane=d accumulates)
    float acc = 0.f;
    #pragma unroll
    for (int jo = 0; jo < 8; ++jo) {
        #pragma unroll 8
        for (int ji = 0; ji < 32; ++ji) {
            float p = __shfl_sync(FULLM, lg[jo], ji);
            acc = fmaf(p, vb[(jo * 32 + ji) * 32 + lane], acc);
        }
    }

    out[((size_t)b * 256 + i) * 256 + (size_t)h * 32 + lane] = acc * inv;
}

extern "C" void kernel_launch(void* const* d_in, const int* in_sizes, int n_in,
                              void* d_out, int out_size)
{
    const float* q    = (const float*)d_in[0];
    const float* k    = (const float*)d_in[1];
    const float* v    = (const float*)d_in[2];
    const float* e    = (const float*)d_in[3];
    const float* mask = (const float*)d_in[4];
    float* out  = (float*)d_out;
    float* eout = out + (size_t)4 * 256 * 256;   // B*N*H*D = 262144

    // 8192 warps total: one per (b,h,i). 8 warps/block -> 1024 blocks.
    edge_attn_kernel<<<1024, 256>>>(q, k, v, e, mask, out, eout);
}

// round 2
// speedup vs baseline: 1.3648x; 1.3648x over previous
#include <cuda_runtime.h>
#include <cstddef>

// B=4, H=8, N=256, D=32
//   scores[b,h,i,j,d] = q[b,h,i,d]*k[b,h,j,d]*edges[b,h,i,j,d]
//   logits = sum_d(scores)/sqrt(D) + mask[b,i,j]; attn = softmax_j
//   out[b,i,h*D+d]       = sum_j attn*v[b,h,j,d]
//   edge_out[b,j,i,h*D+d] = scores
// d_out = [ out (262144) | edge_out (67108864) ]
//
// One warp per (b,h,i). Lane layout: o = lane>>3 selects j-row within a
// 4-row group, c = lane&7 selects d-chunk (4 floats). All global traffic
// is 128-bit per lane.

#define FULLM 0xffffffffu

__global__ __launch_bounds__(256)
void edge_attn_v2(const float* __restrict__ q,
                  const float* __restrict__ k,
                  const float* __restrict__ v,
                  const float* __restrict__ e,
                  const float* __restrict__ mask,
                  float* __restrict__ out,
                  float* __restrict__ eout)
{
    const int lane = threadIdx.x & 31;
    const int o = lane >> 3;      // j-row within 4-row group
    const int c = lane & 7;       // d-chunk: d = 4c .. 4c+3
    const int warp = blockIdx.x * 8 + (threadIdx.x >> 5);  // 0..8191
    const int i  = warp & 255;
    const int bh = warp >> 8;
    const int h  = bh & 7;
    const int b  = bh >> 3;

    const float4 qv = *(const float4*)(q + ((size_t)bh * 256 + i) * 32 + c * 4);
    const float4* __restrict__ kb4 = (const float4*)(k + (size_t)bh * 8192) + c;
    const float4* __restrict__ vb4 = (const float4*)(v + (size_t)bh * 8192) + c;
    const float4* __restrict__ eb4 = (const float4*)(e + ((size_t)bh * 256 + i) * 8192) + c;
    const float*  __restrict__ mr  = mask + ((size_t)b * 256 + i) * 256;
    // edge_out float4 base for (j=0, this lane's d-chunk); j stride = 16384 float4
    float4* __restrict__ eo4 = (float4*)eout
        + ((size_t)b * 4194304 + (size_t)i * 64 + h * 8 + c) / 1;  // element-of-float4 index

    const float SCALE = 0.17677669529663687f;  // 1/sqrt(32)

    float lg[8];

    #pragma unroll
    for (int g = 0; g < 64; ++g) {
        const int j = g * 4 + o;
        float4 e4 = __ldcs(eb4 + (size_t)j * 8);
        float4 k4 = __ldg (kb4 + (size_t)j * 8);
        float4 s;
        s.x = qv.x * k4.x * e4.x;
        s.y = qv.y * k4.y * e4.y;
        s.z = qv.z * k4.z * e4.z;
        s.w = qv.w * k4.w * e4.w;
        __stcs(eo4 + (size_t)j * 16384, s);
        float t = (s.x + s.y) + (s.z + s.w);
        t += __shfl_xor_sync(FULLM, t, 1);
        t += __shfl_xor_sync(FULLM, t, 2);
        t += __shfl_xor_sync(FULLM, t, 4);
        // keeper lane for this group: c == g&7.  lane (o,c) ends holding
        // logits for j = 32t + 4c + o, t = 0..7 -> each j on exactly one lane.
        if (c == (g & 7)) lg[g >> 3] = t * SCALE + __ldg(mr + j);
    }

    // softmax over all 256 logits (8 per lane, distinct across lanes)
    float m = lg[0];
    #pragma unroll
    for (int r = 1; r < 8; ++r) m = fmaxf(m, lg[r]);
    #pragma unroll
    for (int off = 16; off; off >>= 1) m = fmaxf(m, __shfl_xor_sync(FULLM, m, off));

    float ssum = 0.f;
    #pragma unroll
    for (int r = 0; r < 8; ++r) { lg[r] = __expf(lg[r] - m); ssum += lg[r]; }
    #pragma unroll
    for (int off = 16; off; off >>= 1) ssum += __shfl_xor_sync(FULLM, ssum, off);
    const float inv = 1.0f / ssum;

    // out = attn @ v ; lane accumulates d-chunk c over j = 4g + o
    float4 acc = make_float4(0.f, 0.f, 0.f, 0.f);
    #pragma unroll
    for (int g = 0; g < 64; ++g) {
        const int j = g * 4 + o;
        // p(j=4g+o) lives at lane (o, g&7) in register lg[g>>3]
        float p = __shfl_sync(FULLM, lg[g >> 3], (lane & 24) | (g & 7));
        float4 v4 = __ldg(vb4 + (size_t)j * 8);
        acc.x = fmaf(p, v4.x, acc.x);
        acc.y = fmaf(p, v4.y, acc.y);
        acc.z = fmaf(p, v4.z, acc.z);
        acc.w = fmaf(p, v4.w, acc.w);
    }
    // combine the 4 octets (j mod 4 partitions)
    #pragma unroll
    for (int off = 8; off <= 16; off <<= 1) {
        acc.x += __shfl_xor_sync(FULLM, acc.x, off);
        acc.y += __shfl_xor_sync(FULLM, acc.y, off);
        acc.z += __shfl_xor_sync(FULLM, acc.z, off);
        acc.w += __shfl_xor_sync(FULLM, acc.w, off);
    }
    if (o == 0) {
        float4 r = make_float4(acc.x * inv, acc.y * inv, acc.z * inv, acc.w * inv);
        *(float4*)(out + ((size_t)b * 256 + i) * 256 + h * 32 + c * 4) = r;
    }
}

extern "C" void kernel_launch(void* const* d_in, const int* in_sizes, int n_in,
                              void* d_out, int out_size)
{
    const float* q    = (const float*)d_in[0];
    const float* k    = (const float*)d_in[1];
    const float* v    = (const float*)d_in[2];
    const float* e    = (const float*)d_in[3];
    const float* mask = (const float*)d_in[4];
    float* out  = (float*)d_out;
    float* eout = out + (size_t)4 * 256 * 256;  // 262144

    edge_attn_v2<<<1024, 256>>>(q, k, v, e, mask, out, eout);
}